// round 6
// baseline (speedup 1.0000x reference)
#include <cuda_runtime.h>
#include <cuda_bf16.h>
#include <cstdint>

// Problem constants
#define NUM_QT   65
#define NUM_OT   151
#define PAIR_NUM 90
#define BATCH    8192
#define BOX      10
#define TOTAL_ELEMS (NUM_QT * PAIR_NUM * NUM_OT * NUM_OT)  // 133,385,850

// ---------------------------------------------------------------------------
// Scatter-add attention products.
// One thread per (batch, pair). pair p -> i = p/9, j' = p%9, j = j' + (j' >= i).
// out[qt[b]][p][obj_label[b,j]][obj_label[b,i]] += att[b,i]*att[b,j]
// atomicAdd result unused -> ptxas emits REDG (fire-and-forget).
// ---------------------------------------------------------------------------
__global__ void __launch_bounds__(256) scatter_kernel(
    const int* __restrict__ obj_label,
    const int* __restrict__ qus_type,
    const float* __restrict__ attention,
    float* __restrict__ out)
{
    int idx = blockIdx.x * blockDim.x + threadIdx.x;
    if (idx >= BATCH * PAIR_NUM) return;

    int b = idx / PAIR_NUM;
    int p = idx - b * PAIR_NUM;
    int i = p / (BOX - 1);
    int jr = p - i * (BOX - 1);
    int j = jr + (jr >= i ? 1 : 0);

    int qt  = __ldg(&qus_type[b]);
    int oli = __ldg(&obj_label[b * BOX + i]);
    int olj = __ldg(&obj_label[b * BOX + j]);
    float ai = __ldg(&attention[b * BOX + i]);
    float aj = __ldg(&attention[b * BOX + j]);

    // offset = ((qt*PAIR + p)*NUM_OT + ol1)*NUM_OT + ol2, ol1=label[j], ol2=label[i]
    long long off = ((long long)(qt * PAIR_NUM + p) * NUM_OT + olj) * NUM_OT + oli;
    atomicAdd(out + off, ai * aj);
}

// ---------------------------------------------------------------------------
// Launch.
// Inputs (metadata order matching setup_inputs):
//   d_in[0] = obj_label    int32   [8192,10]
//   d_in[1] = qus_type     int32   [8192]
//   d_in[2] = attention    float32 [8192,10]
//   d_in[3] = score_matrix float32 [65,90,151,151]
//
// Copy is done with cudaMemcpyAsync DtoD (explicitly allowed + capturable):
// becomes a memcpy node executed by the driver's tuned copy path instead of
// an SM kernel bound by the LTS cap.
// ---------------------------------------------------------------------------
extern "C" void kernel_launch(void* const* d_in, const int* in_sizes, int n_in,
                              void* d_out, int out_size)
{
    const int*   obj_label = (const int*)d_in[0];
    const int*   qus_type  = (const int*)d_in[1];
    const float* attention = (const float*)d_in[2];
    const float* score     = (const float*)d_in[3];
    float*       out       = (float*)d_out;

    // Bulk copy score_matrix -> out (533.5 MB) on the default (capture) stream.
    cudaMemcpyAsync(out, score, (size_t)TOTAL_ELEMS * sizeof(float),
                    cudaMemcpyDeviceToDevice, 0);

    // Scatter (stream-ordered after the copy).
    {
        int total = BATCH * PAIR_NUM;  // 737,280
        int threads = 256;
        int blocks = (total + threads - 1) / threads;
        scatter_kernel<<<blocks, threads>>>(obj_label, qus_type, attention, out);
    }
}

// round 8
// speedup vs baseline: 1.9883x; 1.9883x over previous
#include <cuda_runtime.h>
#include <cuda_bf16.h>
#include <cstdint>

// Problem constants
#define NUM_QT   65
#define NUM_OT   151
#define PAIR_NUM 90
#define BATCH    8192
#define BOX      10
#define TOTAL_ELEMS (NUM_QT * PAIR_NUM * NUM_OT * NUM_OT)  // 133,385,850
#define N4_TOTAL (TOTAL_ELEMS / 4)                         // 33,346,462 (tail = 2)
#define NCHUNK   4

// ---------------------------------------------------------------------------
// Copy a float4 range [c4_lo, c4_hi) of score_matrix -> out.
// Last chunk also copies the scalar tail (TOTAL_ELEMS - 4*N4_TOTAL = 2 elems).
// ---------------------------------------------------------------------------
__global__ void __launch_bounds__(256) copy_chunk_kernel(
    const float4* __restrict__ src4,
    float4* __restrict__ dst4,
    const float* __restrict__ src,
    float* __restrict__ dst,
    int c4_lo, int c4_hi, int do_tail)
{
    const int stride = gridDim.x * blockDim.x;
    for (int i = c4_lo + blockIdx.x * blockDim.x + threadIdx.x; i < c4_hi; i += stride) {
        dst4[i] = src4[i];
    }
    if (do_tail && blockIdx.x == 0 && threadIdx.x < (TOTAL_ELEMS - 4 * N4_TOTAL)) {
        int e = 4 * N4_TOTAL + threadIdx.x;
        dst[e] = src[e];
    }
}

// ---------------------------------------------------------------------------
// Scatter-add attention products, restricted to output offsets in [lo, hi).
// One thread per (batch, pair). pair p -> i = p/9, j' = p%9, j = j' + (j' >= i).
// out[qt[b]][p][label[b,j]][label[b,i]] += att[b,i]*att[b,j]
// ---------------------------------------------------------------------------
__global__ void __launch_bounds__(256) scatter_chunk_kernel(
    const int* __restrict__ obj_label,
    const int* __restrict__ qus_type,
    const float* __restrict__ attention,
    float* __restrict__ out,
    long long lo, long long hi)
{
    int idx = blockIdx.x * blockDim.x + threadIdx.x;
    if (idx >= BATCH * PAIR_NUM) return;

    int b = idx / PAIR_NUM;
    int p = idx - b * PAIR_NUM;
    int i = p / (BOX - 1);
    int jr = p - i * (BOX - 1);
    int j = jr + (jr >= i ? 1 : 0);

    int qt  = __ldg(&qus_type[b]);
    int oli = __ldg(&obj_label[b * BOX + i]);
    int olj = __ldg(&obj_label[b * BOX + j]);

    long long off = ((long long)(qt * PAIR_NUM + p) * NUM_OT + olj) * NUM_OT + oli;
    if (off < lo || off >= hi) return;

    float ai = __ldg(&attention[b * BOX + i]);
    float aj = __ldg(&attention[b * BOX + j]);
    atomicAdd(out + off, ai * aj);
}

// ---------------------------------------------------------------------------
// Launch: pipelined copy + scatter.
//   stream 0 (capture/legacy): copy chunk 0..3
//   side stream:               scatter chunk k after copy chunk k's event
// Join side stream back into stream 0 at the end (required for capture).
//
// Inputs (metadata order):
//   d_in[0] = obj_label    int32   [8192,10]
//   d_in[1] = qus_type     int32   [8192]
//   d_in[2] = attention    float32 [8192,10]
//   d_in[3] = score_matrix float32 [65,90,151,151]
// ---------------------------------------------------------------------------
extern "C" void kernel_launch(void* const* d_in, const int* in_sizes, int n_in,
                              void* d_out, int out_size)
{
    const int*   obj_label = (const int*)d_in[0];
    const int*   qus_type  = (const int*)d_in[1];
    const float* attention = (const float*)d_in[2];
    const float* score     = (const float*)d_in[3];
    float*       out       = (float*)d_out;

    // Lazy one-time resource setup (first call = uncaptured correctness run).
    static cudaStream_t s_side = nullptr;
    static cudaEvent_t  ev_copy[NCHUNK];
    static cudaEvent_t  ev_join = nullptr;
    if (s_side == nullptr) {
        cudaStreamCreateWithFlags(&s_side, cudaStreamNonBlocking);
        for (int k = 0; k < NCHUNK; k++)
            cudaEventCreateWithFlags(&ev_copy[k], cudaEventDisableTiming);
        cudaEventCreateWithFlags(&ev_join, cudaEventDisableTiming);
    }

    const int q4 = (N4_TOTAL + NCHUNK - 1) / NCHUNK;   // float4s per chunk
    const int copy_blocks = 148 * 16;
    const int scat_total  = BATCH * PAIR_NUM;          // 737,280
    const int scat_blocks = (scat_total + 255) / 256;

    for (int k = 0; k < NCHUNK; k++) {
        int c4_lo = k * q4;
        int c4_hi = (k + 1) * q4;
        if (c4_hi > N4_TOTAL) c4_hi = N4_TOTAL;
        int last = (k == NCHUNK - 1);

        copy_chunk_kernel<<<copy_blocks, 256, 0, 0>>>(
            (const float4*)score, (float4*)out, score, out, c4_lo, c4_hi, last);
        cudaEventRecord(ev_copy[k], 0);

        cudaStreamWaitEvent(s_side, ev_copy[k], 0);
        long long lo = (long long)c4_lo * 4;
        long long hi = last ? (long long)TOTAL_ELEMS : (long long)c4_hi * 4;
        scatter_chunk_kernel<<<scat_blocks, 256, 0, s_side>>>(
            obj_label, qus_type, attention, out, lo, hi);
    }

    // Join side stream back into the capture origin stream.
    cudaEventRecord(ev_join, s_side);
    cudaStreamWaitEvent(0, ev_join, 0);
}